// round 5
// baseline (speedup 1.0000x reference)
#include <cuda_runtime.h>
#include <cstdint>

#define NB_IMG   16
#define NA       22743
#define NCH      85
#define NCLS     80
#define PRE      1000
#define PADN     1024
#define SORTN    4096
#define CAP      32768
#define NBINS    8192
#define MAXDET   300
#define CONF_TH  0.2f
#define NMS_TH   0.45f

static __device__ __constant__ unsigned B09 = 0x3F666666u; // bits(0.9f)

__device__ unsigned            g_hist[NB_IMG][NBINS];     // zero-initialized; re-zeroed by k_prep
__device__ unsigned            g_candcnt[NB_IMG];         // idem
__device__ unsigned long long  g_cand[NB_IMG][CAP];
__device__ float               g_box[NB_IMG][PADN][4];
__device__ float               g_sbox[NB_IMG][PADN][4];
__device__ float               g_sarea[NB_IMG][PADN];
__device__ float               g_score[NB_IMG][PADN];
__device__ int                 g_label[NB_IMG][PADN];
__device__ unsigned            g_lblbits[NB_IMG][NCLS][32];

// ---------------------------------------------------------------- scan
// Phase A: each thread reads one conf; block-compacts hot anchors (conf>0.9).
// Phase B: one warp per hot anchor scans its 80 classprobs.
// Valid because classprobs <= 1 => fl(p*conf) <= conf, so score>0.9 => conf>0.9.
__global__ void k_scan(const float* __restrict__ preds) {
    __shared__ int      s_hot[256];
    __shared__ float    s_conf[256];
    __shared__ unsigned s_n;
    int img = blockIdx.y;
    int a   = blockIdx.x * 256 + threadIdx.x;
    if (threadIdx.x == 0) s_n = 0;
    __syncthreads();
    float conf = 0.0f;
    if (a < NA) conf = __ldg(preds + ((size_t)img * NA + a) * NCH + 4);
    if (conf > 0.9f) {
        unsigned p = atomicAdd(&s_n, 1u);
        s_hot[p]  = a;
        s_conf[p] = conf;
    }
    __syncthreads();
    int nhot = (int)s_n;
    int wid  = threadIdx.x >> 5, lane = threadIdx.x & 31;
    for (int h = wid; h < nhot; h += 8) {
        int   aa = s_hot[h];
        float cf = s_conf[h];
        const float* pp = preds + ((size_t)img * NA + aa) * NCH + 5;
        float p0 = __ldg(pp + lane);
        float p1 = __ldg(pp + lane + 32);
        float p2 = (lane < 16) ? __ldg(pp + lane + 64) : 0.0f;
        float s0 = p0 * cf, s1 = p1 * cf, s2 = p2 * cf;
        bool e0 = s0 > 0.9f, e1 = s1 > 0.9f, e2 = s2 > 0.9f;
        unsigned b0 = __ballot_sync(0xFFFFFFFFu, e0);
        unsigned b1 = __ballot_sync(0xFFFFFFFFu, e1);
        unsigned b2 = __ballot_sync(0xFFFFFFFFu, e2);
        unsigned tot = __popc(b0) + __popc(b1) + __popc(b2);
        if (tot) {
            unsigned base = 0;
            if (lane == 0) base = atomicAdd(&g_candcnt[img], tot);
            base = __shfl_sync(0xFFFFFFFFu, base, 0);
            unsigned lt = (1u << lane) - 1u;
            unsigned fb = (unsigned)aa * NCLS;
            if (e0) {
                unsigned bits = __float_as_uint(s0);
                unsigned bin = (bits - (B09 + 1u)) >> 8; if (bin > NBINS - 1) bin = NBINS - 1;
                atomicAdd(&g_hist[img][bin], 1u);
                unsigned slot = base + __popc(b0 & lt);
                if (slot < CAP)
                    g_cand[img][slot] = ((unsigned long long)bits << 32) |
                        (unsigned long long)(0xFFFFFFFFu - (fb + lane));
            }
            if (e1) {
                unsigned bits = __float_as_uint(s1);
                unsigned bin = (bits - (B09 + 1u)) >> 8; if (bin > NBINS - 1) bin = NBINS - 1;
                atomicAdd(&g_hist[img][bin], 1u);
                unsigned slot = base + __popc(b0) + __popc(b1 & lt);
                if (slot < CAP)
                    g_cand[img][slot] = ((unsigned long long)bits << 32) |
                        (unsigned long long)(0xFFFFFFFFu - (fb + lane + 32u));
            }
            if (e2) {
                unsigned bits = __float_as_uint(s2);
                unsigned bin = (bits - (B09 + 1u)) >> 8; if (bin > NBINS - 1) bin = NBINS - 1;
                atomicAdd(&g_hist[img][bin], 1u);
                unsigned slot = base + __popc(b0) + __popc(b1) + __popc(b2 & lt);
                if (slot < CAP)
                    g_cand[img][slot] = ((unsigned long long)bits << 32) |
                        (unsigned long long)(0xFFFFFFFFu - (fb + lane + 64u));
            }
        }
    }
}

// ---------------------------------------------------------------- prep: threshold + (fallback) + compact + sort + gather
__global__ void __launch_bounds__(1024, 1) k_prep(const float* __restrict__ preds) {
    __shared__ unsigned long long keys[SORTN];          // 32KB; aliased as hist first
    __shared__ unsigned csum[256];
    __shared__ int      s_fb;
    __shared__ unsigned s_thr;
    __shared__ unsigned scnt;
    __shared__ float    wmax[32];
    __shared__ float    s_maxv;
    __shared__ unsigned sbits[NCLS][32];
    unsigned* sh = (unsigned*)keys;                     // NBINS*4 == SORTN*8
    int img = blockIdx.x, tid = threadIdx.x;

    // ---- threshold from fine hist ----
    for (int i = tid; i < NBINS; i += 1024) sh[i] = g_hist[img][i];
    __syncthreads();
    if (tid < 256) {
        unsigned ssum = 0;
        for (int j = 0; j < 32; j++) ssum += sh[tid * 32 + j];
        csum[tid] = ssum;
    }
    __syncthreads();
    if (tid == 0) {
        unsigned total = 0;
        for (int c = 0; c < 256; c++) total += csum[c];
        if (total >= PRE) {
            unsigned acc = 0, M = 0;
            int bstar = 0;
            for (int c = 255; c >= 0; c--) {
                if (acc + csum[c] >= PRE) {
                    for (int b = c * 32 + 31; b >= c * 32; b--) {
                        acc += sh[b];
                        if (acc >= PRE) { bstar = b; M = acc; break; }
                    }
                    break;
                }
                acc += csum[c];
            }
            if (M > SORTN) bstar++;                    // pathological ties
            s_thr = B09 + 1u + ((unsigned)bstar << 8);
            s_fb  = 0;
        } else {
            g_candcnt[img] = 0u;
            s_fb = 1;
        }
    }
    __syncthreads();

    // ---- fallback (rare): full-range in-block histogram + re-compact ----
    if (s_fb) {
        for (int i = tid; i < NBINS; i += 1024) sh[i] = 0u;
        __syncthreads();
        const float* base = preds + (size_t)img * NA * NCH;
        for (int a = tid; a < NA; a += 1024) {
            const float* p = base + (size_t)a * NCH;
            float conf = p[4];
            for (int c = 0; c < NCLS; c++) {
                float s = p[5 + c] * conf;
                if (s > CONF_TH) {
                    unsigned bin = __float_as_uint(s) >> 13;
                    if (bin > NBINS - 1) bin = NBINS - 1;
                    atomicAdd(&sh[bin], 1u);
                }
            }
        }
        __syncthreads();
        if (tid < 256) {
            unsigned ssum = 0;
            for (int j = 0; j < 32; j++) ssum += sh[tid * 32 + j];
            csum[tid] = ssum;
        }
        __syncthreads();
        if (tid == 0) {
            unsigned total = 0;
            for (int c = 0; c < 256; c++) total += csum[c];
            unsigned thr = 0;
            if (total >= PRE) {
                unsigned acc = 0, M = 0;
                int bstar = 0;
                for (int c = 255; c >= 0; c--) {
                    if (acc + csum[c] >= PRE) {
                        for (int b = c * 32 + 31; b >= c * 32; b--) {
                            acc += sh[b];
                            if (acc >= PRE) { bstar = b; M = acc; break; }
                        }
                        break;
                    }
                    acc += csum[c];
                }
                if (M > SORTN) bstar++;
                thr = (unsigned)bstar << 13;
            }
            s_thr = thr;
        }
        __syncthreads();
        unsigned thr = s_thr;
        for (int a = tid; a < NA; a += 1024) {
            const float* p = base + (size_t)a * NCH;
            float conf = p[4];
            unsigned fb = (unsigned)a * NCLS;
            for (int c = 0; c < NCLS; c++) {
                float s = p[5 + c] * conf;
                if (s > CONF_TH) {
                    unsigned bits = __float_as_uint(s);
                    if (bits >= thr) {
                        unsigned pos = atomicAdd(&g_candcnt[img], 1u);
                        if (pos < CAP)
                            g_cand[img][pos] = ((unsigned long long)bits << 32) |
                                (unsigned long long)(0xFFFFFFFFu - (fb + (unsigned)c));
                    }
                }
            }
        }
        __syncthreads();
    }

    // ---- compact candidates >= thr into keys (hist no longer needed) ----
    unsigned thr = s_thr;
    unsigned n   = g_candcnt[img]; if (n > CAP) n = CAP;
    if (tid == 0) scnt = 0;
    for (int i = tid; i < SORTN; i += 1024) keys[i] = 0ULL;
    for (int i = tid; i < NCLS * 32; i += 1024) (&sbits[0][0])[i] = 0u;
    __syncthreads();
    for (unsigned i = tid; i < n; i += 1024) {
        unsigned long long k = g_cand[img][i];
        if ((unsigned)(k >> 32) >= thr) {
            unsigned pos = atomicAdd(&scnt, 1u);
            if (pos < SORTN) keys[pos] = k;
        }
    }
    __syncthreads();

    // ---- sort descending ----
    if (scnt <= 1024u) {
        // hybrid: 1 key/thread; j>=32 via smem, j<32 via shuffles
        unsigned long long x = keys[tid];
        for (int k2 = 2; k2 <= 1024; k2 <<= 1) {
            bool up = (tid & k2) != 0;
            for (int j = k2 >> 1; j >= 32; j >>= 1) {
                unsigned long long y = keys[tid ^ j];
                bool isLo = (tid & j) == 0;
                bool takeMin = isLo ? up : !up;
                unsigned long long nx = takeMin ? (x < y ? x : y) : (x > y ? x : y);
                __syncthreads();
                keys[tid] = nx; x = nx;
                __syncthreads();
            }
            int j0 = (k2 >> 1 < 16) ? (k2 >> 1) : 16;
            for (int j = j0; j >= 1; j >>= 1) {
                unsigned long long y = __shfl_xor_sync(0xFFFFFFFFu, x, j);
                bool isLo = (tid & j) == 0;
                bool takeMin = isLo ? up : !up;
                x = takeMin ? (x < y ? x : y) : (x > y ? x : y);
            }
            keys[tid] = x;
            __syncthreads();
        }
    } else {
        int n2 = (scnt <= 2048u) ? 2048 : SORTN;
        for (int k2 = 2; k2 <= n2; k2 <<= 1)
            for (int j = k2 >> 1; j > 0; j >>= 1) {
                for (int idx = tid; idx < n2; idx += 1024) {
                    int ixj = idx ^ j;
                    if (ixj > idx) {
                        unsigned long long x = keys[idx], y = keys[ixj];
                        bool asc  = (idx & k2) != 0;
                        bool sw   = asc ? (x > y) : (x < y);
                        if (sw) { keys[idx] = y; keys[ixj] = x; }
                    }
                }
                __syncthreads();
            }
    }

    // ---- decode + gather boxes + class-shift ----
    float bx0 = 0.f, bx1 = 0.f, bx2 = 0.f, bx3 = 0.f, s = 0.f;
    int lab = 0;
    float localmax = 0.0f;
    if (tid < PRE) {
        unsigned long long k = keys[tid];
        if (k != 0ULL) {
            unsigned bits = (unsigned)(k >> 32);
            s = __uint_as_float(bits);
            unsigned flat = 0xFFFFFFFFu - (unsigned)(k & 0xFFFFFFFFull);
            int anc = (int)(flat / NCLS);
            lab     = (int)(flat % NCLS);
            const float* bp = preds + ((size_t)(img * NA + anc)) * NCH;
            bx0 = bp[0]; bx1 = bp[1]; bx2 = bp[2]; bx3 = bp[3];
        }
        localmax = fmaxf(fmaxf(bx0, bx1), fmaxf(bx2, bx3));
        g_score[img][tid]  = s;
        g_label[img][tid]  = lab;
        g_box[img][tid][0] = bx0; g_box[img][tid][1] = bx1;
        g_box[img][tid][2] = bx2; g_box[img][tid][3] = bx3;
        atomicOr(&sbits[lab][tid >> 5], 1u << (tid & 31));
    }
    for (int o = 16; o; o >>= 1) localmax = fmaxf(localmax, __shfl_xor_sync(0xFFFFFFFFu, localmax, o));
    if ((tid & 31) == 0) wmax[tid >> 5] = localmax;
    __syncthreads();
    if (tid < 32) {
        float v = wmax[tid];
        for (int o = 16; o; o >>= 1) v = fmaxf(v, __shfl_xor_sync(0xFFFFFFFFu, v, o));
        if (tid == 0) s_maxv = v;
    }
    __syncthreads();
    float maxv = s_maxv;
    if (tid < PRE) {
        float shift = (float)lab * (maxv + 1.0f);
        float x1 = bx0 + shift, y1 = bx1 + shift, x2 = bx2 + shift, y2 = bx3 + shift;
        g_sbox[img][tid][0] = x1; g_sbox[img][tid][1] = y1;
        g_sbox[img][tid][2] = x2; g_sbox[img][tid][3] = y2;
        g_sarea[img][tid] = fmaxf(x2 - x1, 0.0f) * fmaxf(y2 - y1, 0.0f);
    }
    for (int i = tid; i < NCLS * 32; i += 1024)
        (&g_lblbits[img][0][0])[i] = (&sbits[0][0])[i];

    // ---- restore zeroed state for next replay ----
    for (int i = tid; i < NBINS; i += 1024) g_hist[img][i] = 0u;
    if (tid == 0) g_candcnt[img] = 0u;
}

// ---------------------------------------------------------------- mask + serial NMS + output (fused)
__global__ void __launch_bounds__(1024, 1) k_final(float* __restrict__ dout) {
    extern __shared__ unsigned smask[];   // PRE*32 words = 125 KB
    __shared__ float4   sb[PADN];
    __shared__ float4   sbx[PADN];
    __shared__ float    sa[PADN];
    __shared__ float    ssc[PADN];
    __shared__ int      sl[PADN];
    __shared__ unsigned slb[NCLS][32];
    int img = blockIdx.x, tid = threadIdx.x;
    for (int i = tid; i < PADN; i += 1024) {
        sb[i]  = ((const float4*)g_sbox[img])[i];
        sbx[i] = ((const float4*)g_box[img])[i];
        sa[i]  = g_sarea[img][i];
        ssc[i] = g_score[img][i];
        sl[i]  = g_label[img][i];
    }
    for (int i = tid; i < NCLS * 32; i += 1024)
        (&slb[0][0])[i] = (&g_lblbits[img][0][0])[i];
    __syncthreads();

    // ---- per-row suppression masks (same-label pairs only) ----
    if (tid < PRE) {
        int i = tid;
        int l = sl[i];
        float4 bi = sb[i];
        float  ai = sa[i];
        int wi = i >> 5;
        for (int w = 0; w < 32; w++) {
            unsigned word = 0u;
            if (w >= wi) {
                unsigned cand = slb[l][w];
                if (w == wi) cand &= ~((2u << (i & 31)) - 1u);
                while (cand) {
                    int bb = __ffs(cand) - 1; cand &= cand - 1;
                    int j = w * 32 + bb;
                    float4 bj = sb[j];
                    float ix1 = fmaxf(bi.x, bj.x), iy1 = fmaxf(bi.y, bj.y);
                    float ix2 = fminf(bi.z, bj.z), iy2 = fminf(bi.w, bj.w);
                    float inter = fmaxf(ix2 - ix1, 0.0f) * fmaxf(iy2 - iy1, 0.0f);
                    float den = ai + sa[j];
                    den = den - inter;
                    den = den + 1e-7f;
                    float iou = __fdiv_rn(inter, den);
                    if (iou > NMS_TH) word |= (1u << bb);
                }
            }
            smask[i * 32 + w] = word;
        }
    }
    __syncthreads();

    // ---- serial greedy NMS (one warp) + ordered output ----
    if (tid < 32) {
        int w = tid;
        unsigned valid = 0u;
        for (int b = 0; b < 32; b++) {
            int i = w * 32 + b;
            if (i < PRE && ssc[i] > CONF_TH) valid |= (1u << b);
        }
        unsigned removed = 0u, mykeep = 0u;
        for (int W = 0; W < 32; W++) {
            unsigned kw = 0u;
            if (w == W) {
                unsigned rW = removed;
                for (int b = 0; b < 32; b++) {
                    int i = W * 32 + b;
                    if (i >= PRE) break;
                    if (((valid >> b) & 1u) && !((rW >> b) & 1u)) {
                        kw |= (1u << b);
                        rW |= smask[i * 32 + W];
                    }
                }
                removed = rW;
            }
            kw = __shfl_sync(0xFFFFFFFFu, kw, W);
            unsigned m = kw;
            while (m) {
                int b = __ffs(m) - 1; m &= m - 1;
                removed |= smask[(W * 32 + b) * 32 + w];
            }
            if (w == W) mykeep = kw;
            __syncwarp();
        }
        int cnt = __popc(mykeep);
        int pre = cnt;
        for (int o = 1; o < 32; o <<= 1) {
            int v = __shfl_up_sync(0xFFFFFFFFu, pre, o);
            if (w >= o) pre += v;
        }
        int total = __shfl_sync(0xFFFFFFFFu, pre, 31);
        pre -= cnt;
        float* ob = dout + (size_t)img * MAXDET * 4;
        float* os = dout + (size_t)NB_IMG * MAXDET * 4 + (size_t)img * MAXDET;
        float* ol = dout + (size_t)NB_IMG * MAXDET * 5 + (size_t)img * MAXDET;
        unsigned m = mykeep;
        int r = pre;
        while (m) {
            int b = __ffs(m) - 1; m &= m - 1;
            if (r < MAXDET) {
                int i = w * 32 + b;
                float4 bx = sbx[i];
                ob[r * 4 + 0] = bx.x;
                ob[r * 4 + 1] = bx.y;
                ob[r * 4 + 2] = bx.z;
                ob[r * 4 + 3] = bx.w;
                os[r] = ssc[i];
                ol[r] = (float)sl[i];
            }
            r++;
        }
        for (int r2 = total + w; r2 < MAXDET; r2 += 32) {
            ob[r2 * 4 + 0] = 0.0f; ob[r2 * 4 + 1] = 0.0f;
            ob[r2 * 4 + 2] = 0.0f; ob[r2 * 4 + 3] = 0.0f;
            os[r2] = 0.0f;
            ol[r2] = -1.0f;
        }
    }
}

// ---------------------------------------------------------------- launch
extern "C" void kernel_launch(void* const* d_in, const int* in_sizes, int n_in,
                              void* d_out, int out_size) {
    (void)in_sizes; (void)n_in; (void)out_size;
    const float* preds = (const float*)d_in[0];
    float* out = (float*)d_out;

    cudaFuncSetAttribute(k_final, cudaFuncAttributeMaxDynamicSharedMemorySize, 132 * 1024);

    k_scan<<<dim3((NA + 255) / 256, NB_IMG), 256>>>(preds);
    k_prep<<<NB_IMG, 1024>>>(preds);
    k_final<<<NB_IMG, 1024, PRE * 32 * sizeof(unsigned)>>>(out);
}